// round 13
// baseline (speedup 1.0000x reference)
#include <cuda_runtime.h>
#include <cuda_fp16.h>

// Problem constants
#define Bn   4
#define CHI  256
#define CHO  256
#define Hd   96
#define Wd   96
#define Kt   9
#define HW   (Hd*Wd)          // 9216
#define Mpx  (Bn*HW)          // 36864
#define KD   (CHI*Kt)         // 2304
#define BN_EPS 1e-5f

// Bilinear tap: 4 clamped offsets + 4 corner weights (validity+mask folded in)
struct __align__(16) TapParam {
    int   o00, o01, o10, o11;
    float w00, w01, w10, w11;
};

// Scratch (device globals: allocation-guard-safe)
__device__ TapParam       g_params[Bn * Kt * HW];                       // ~10.6 MB
__device__ __align__(16) unsigned short g_cols[(size_t)Mpx * KD];       // 170 MB fp16
__device__ __align__(16) unsigned short g_wh[(size_t)CHO * KD];         // 1.18 MB
__device__ __align__(16) unsigned short g_wl[(size_t)CHO * KD];
__device__ float          g_sums[2 * CHO];                              // s, s2 partials
__device__ float          g_stats[2 * CHO];                             // scale, shift

// ---------------------------------------------------------------------------
// Kernel 1: offset conv (256->27, 3x3, pad 1) -> TapParams.
// 1 px/thread, 256 threads (8 warps/SM for latency hiding), float4 smem weights.
// ---------------------------------------------------------------------------
#define OC  27
#define OCP 32

__global__ void __launch_bounds__(256) k_offset(
    const float* __restrict__ x,
    const float* __restrict__ w_off,
    const float* __restrict__ b_off)
{
    __shared__ float ws[32 * 9 * OCP];
    int p  = blockIdx.x * 256 + threadIdx.x;   // grid.x = Mpx/256 = 144
    int b  = p / HW, hw = p % HW;
    int h  = hw / Wd, w = hw % Wd;

    float acc[28];
#pragma unroll
    for (int i = 0; i < 28; i++) acc[i] = 0.f;

    for (int c0 = 0; c0 < CHI; c0 += 32) {
        __syncthreads();
        for (int i = threadIdx.x; i < 32 * 9 * OC; i += 256) {
            int oc = i % OC;
            int ct = i / OC;
            ws[ct * OCP + oc] = w_off[(oc * CHI + c0 + ct / 9) * 9 + (ct % 9)];
        }
        __syncthreads();

        const float* xb = x + ((size_t)b * CHI + c0) * HW;
        for (int cc = 0; cc < 32; cc++) {
            const float* xc = xb + cc * HW;
            float xv[9];
#pragma unroll
            for (int ty = 0; ty < 3; ty++) {
                int y = h + ty - 1;
                bool yv = ((unsigned)y < (unsigned)Hd);
#pragma unroll
                for (int tx = 0; tx < 3; tx++) {
                    int xx = w + tx - 1;
                    xv[ty * 3 + tx] =
                        (yv && (unsigned)xx < (unsigned)Wd) ? xc[y * Wd + xx] : 0.f;
                }
            }
#pragma unroll
            for (int t = 0; t < 9; t++) {
                const float4* wr4 = (const float4*)&ws[(cc * 9 + t) * OCP];
                float xvt = xv[t];
#pragma unroll
                for (int j = 0; j < 7; j++) {
                    float4 w4 = wr4[j];
                    acc[j * 4 + 0] += w4.x * xvt;
                    acc[j * 4 + 1] += w4.y * xvt;
                    acc[j * 4 + 2] += w4.z * xvt;
                    acc[j * 4 + 3] += w4.w * xvt;
                }
            }
        }
    }

#pragma unroll
    for (int k = 0; k < Kt; k++) {
        float dy = acc[2 * k]     + b_off[2 * k];
        float dx = acc[2 * k + 1] + b_off[2 * k + 1];
        float mz = acc[18 + k]    + b_off[18 + k];
        float m  = 1.f / (1.f + expf(-mz));

        float py = dy + (float)(h + k / 3 - 1);
        float px = dx + (float)(w + k % 3 - 1);
        float fy = floorf(py), fx = floorf(px);
        float ly = py - fy,    lx = px - fx;
        int y0 = (int)fy, x0 = (int)fx, y1 = y0 + 1, x1 = x0 + 1;

        float vy0 = ((unsigned)y0 < (unsigned)Hd) ? 1.f : 0.f;
        float vy1 = ((unsigned)y1 < (unsigned)Hd) ? 1.f : 0.f;
        float vx0 = ((unsigned)x0 < (unsigned)Wd) ? 1.f : 0.f;
        float vx1 = ((unsigned)x1 < (unsigned)Wd) ? 1.f : 0.f;

        int y0c = min(max(y0, 0), Hd - 1), y1c = min(max(y1, 0), Hd - 1);
        int x0c = min(max(x0, 0), Wd - 1), x1c = min(max(x1, 0), Wd - 1);

        TapParam tp;
        tp.o00 = y0c * Wd + x0c;  tp.o01 = y0c * Wd + x1c;
        tp.o10 = y1c * Wd + x0c;  tp.o11 = y1c * Wd + x1c;
        tp.w00 = (1.f - ly) * (1.f - lx) * vy0 * vx0 * m;
        tp.w01 = (1.f - ly) * lx         * vy0 * vx1 * m;
        tp.w10 = ly * (1.f - lx)         * vy1 * vx0 * m;
        tp.w11 = ly * lx                 * vy1 * vx1 * m;
        g_params[(b * Kt + k) * HW + hw] = tp;
    }
}

// ---------------------------------------------------------------------------
// Kernel 2: split w_conv into fp16 hi/lo, [CHO][KD] K-major.
// Block 0 also zeros ALL 512 g_sums entries (2 per thread).
// ---------------------------------------------------------------------------
__global__ void __launch_bounds__(256) k_wsplit(const float* __restrict__ w)
{
    int i = blockIdx.x * 256 + threadIdx.x;
    if (blockIdx.x == 0) {
        g_sums[threadIdx.x]       = 0.f;
        g_sums[threadIdx.x + 256] = 0.f;
    }
    float v = w[i];
    __half hh = __float2half_rn(v);
    float r = v - __half2float(hh);
    __half hl = __float2half_rn(r);
    g_wh[i] = __half_as_ushort(hh);
    g_wl[i] = __half_as_ushort(hl);
}

// ---------------------------------------------------------------------------
// Kernel 3: deformable im2col -> fp16, K-major [pixel][KD].
// Thread = (pixel, 8-channel chunk): wide parallelism.
// ---------------------------------------------------------------------------
__global__ void __launch_bounds__(256) k_cols(const float* __restrict__ x)
{
    int p  = blockIdx.x * 256 + threadIdx.x;   // grid.x = 144
    int c0 = blockIdx.y * 8;                   // grid.y = 32
    int b  = p / HW, hw = p % HW;
    const float* xb = x + ((size_t)b * CHI + c0) * HW;

    unsigned buf[36];
#pragma unroll
    for (int j = 0; j < 36; j++) buf[j] = 0u;

#pragma unroll
    for (int k = 0; k < Kt; k++) {
        TapParam tp = g_params[(b * Kt + k) * HW + hw];
#pragma unroll
        for (int cc = 0; cc < 8; cc++) {
            const float* xc = xb + cc * HW;
            float v = tp.w00 * __ldg(xc + tp.o00) + tp.w01 * __ldg(xc + tp.o01)
                    + tp.w10 * __ldg(xc + tp.o10) + tp.w11 * __ldg(xc + tp.o11);
            unsigned hb = (unsigned)__half_as_ushort(__float2half_rn(v));
            int e = cc * 9 + k;
            buf[e >> 1] |= hb << ((e & 1) * 16);
        }
    }

    uint4* dh = (uint4*)(g_cols + (size_t)p * KD + c0 * 9);
#pragma unroll
    for (int j = 0; j < 9; j++)
        dh[j] = make_uint4(buf[4*j], buf[4*j+1], buf[4*j+2], buf[4*j+3]);
}

// ---------------------------------------------------------------------------
// Kernel 4: mma.sync fp16 GEMM, split-A 2-product fp32 accumulation.
// CTA: 128 CHO x 128 pixels. 8 warps, warp tile 64x32. BK=64, 3-stage cp.async.
// Single __syncthreads per chunk. Epilogue: bias, NCHW store, BN partial sums.
// ---------------------------------------------------------------------------
#define NCHUNK 36
#define TILEB  16384                 // 128 rows x 128 bytes
#define STAGEB (3 * TILEB)           // Ahi Alo B
#define NSTAGE 3
#define SMEMSZ (NSTAGE * STAGEB)     // 147456

#define LDM4(R0,R1,R2,R3,ADDR) \
    asm volatile("ldmatrix.sync.aligned.m8n8.x4.shared.b16 {%0,%1,%2,%3}, [%4];" \
                 : "=r"(R0),"=r"(R1),"=r"(R2),"=r"(R3) : "r"(ADDR))

#define MMA(C,A,B0,B1) \
    asm volatile("mma.sync.aligned.m16n8k16.row.col.f32.f16.f16.f32 " \
                 "{%0,%1,%2,%3},{%4,%5,%6,%7},{%8,%9},{%0,%1,%2,%3};" \
                 : "+f"((C)[0]),"+f"((C)[1]),"+f"((C)[2]),"+f"((C)[3]) \
                 : "r"((A)[0]),"r"((A)[1]),"r"((A)[2]),"r"((A)[3]),   \
                   "r"(B0),"r"(B1))

__device__ __forceinline__ void load_chunk(unsigned smBase, int stage, int chunk,
                                           int oBase, int pBase, int tid)
{
    unsigned dstBase = smBase + stage * STAGEB;
    int k0 = chunk * 64;
#pragma unroll
    for (int j = 0; j < 12; j++) {
        int i    = tid + j * 256;        // 0..3071
        int tile = i >> 10;              // 0..2
        int row  = (i >> 3) & 127;
        int u    = i & 7;
        const unsigned short* src;
        int rbase;
        if (tile == 0)      { src = g_wh;   rbase = oBase; }
        else if (tile == 1) { src = g_wl;   rbase = oBase; }
        else                { src = g_cols; rbase = pBase; }
        const char* g = (const char*)src + ((size_t)(rbase + row) * KD + k0) * 2 + u * 16;
        unsigned d = dstBase + tile * TILEB + row * 128 + ((u ^ (row & 7)) * 16);
        asm volatile("cp.async.cg.shared.global [%0], [%1], 16;" :: "r"(d), "l"(g));
    }
    asm volatile("cp.async.commit_group;" ::: "memory");
}

__global__ void __launch_bounds__(256, 1) k_gemm(
    const float* __restrict__ bconv,
    float* __restrict__ out)
{
    extern __shared__ char sm[];
    unsigned smBase = (unsigned)__cvta_generic_to_shared(sm);

    int tid = threadIdx.x, lane = tid & 31, wid = tid >> 5;
    int wm = wid & 1;            // m half (64 rows)
    int wn = wid >> 1;           // n quarter (32 pixels)
    int pBase = blockIdx.x * 128;
    int oBase = blockIdx.y * 128;

    // ldmatrix per-lane geometry
    unsigned aRL = ((lane >> 3) & 1) * 8 + (lane & 7);   // A: row-in-tile16
    unsigned aU  = lane >> 4;                            // A: k8 unit
    unsigned bRL = ((lane >> 4) & 1) * 8 + (lane & 7);   // B: row-in-tile16
    unsigned bU  = (lane >> 3) & 1;                      // B: k8 unit
    unsigned aRowOff[4], bRowOff[2];
#pragma unroll
    for (int mt = 0; mt < 4; mt++) aRowOff[mt] = (wm * 64 + mt * 16 + aRL) * 128;
#pragma unroll
    for (int nt = 0; nt < 2; nt++) bRowOff[nt] = (wn * 32 + nt * 16 + bRL) * 128;
    unsigned aMsk = aRL & 7, bMsk = bRL & 7;

    float c[16][4];
#pragma unroll
    for (int i = 0; i < 16; i++)
#pragma unroll
        for (int j = 0; j < 4; j++) c[i][j] = 0.f;

    load_chunk(smBase, 0, 0, oBase, pBase, tid);
    load_chunk(smBase, 1, 1, oBase, pBase, tid);

    for (int ch = 0; ch < NCHUNK; ch++) {
        int st = ch % NSTAGE;
        if (ch + 1 < NCHUNK) {
            asm volatile("cp.async.wait_group 1;" ::: "memory");
        } else {
            asm volatile("cp.async.wait_group 0;" ::: "memory");
        }
        __syncthreads();
        if (ch + 2 < NCHUNK)
            load_chunk(smBase, (ch + 2) % NSTAGE, ch + 2, oBase, pBase, tid);

        unsigned base = smBase + st * STAGEB;
        unsigned sAh = base, sAl = base + TILEB, sB = base + 2 * TILEB;

#pragma unroll
        for (int kk = 0; kk < 4; kk++) {
            unsigned ua = ((kk * 2 + aU) ^ aMsk) * 16;
            unsigned ub = ((kk * 2 + bU) ^ bMsk) * 16;

            unsigned ah[4][4], al[4][4], bh[2][4];
#pragma unroll
            for (int mt = 0; mt < 4; mt++) {
                LDM4(ah[mt][0], ah[mt][1], ah[mt][2], ah[mt][3], sAh + aRowOff[mt] + ua);
                LDM4(al[mt][0], al[mt][1], al[mt][2], al[mt][3], sAl + aRowOff[mt] + ua);
            }
#pragma unroll
            for (int nt = 0; nt < 2; nt++)
                LDM4(bh[nt][0], bh[nt][1], bh[nt][2], bh[nt][3], sB + bRowOff[nt] + ub);

#pragma unroll
            for (int mt = 0; mt < 4; mt++)
#pragma unroll
                for (int nt = 0; nt < 4; nt++) {
                    int n2 = nt >> 1, jj = (nt & 1) * 2;
                    float* cc = c[mt * 4 + nt];
                    MMA(cc, ah[mt], bh[n2][jj], bh[n2][jj + 1]);
                    MMA(cc, al[mt], bh[n2][jj], bh[n2][jj + 1]);
                }
        }
        __syncthreads();
    }

    // Epilogue: + bias, NCHW stores, BN partial sums (s, s2) per channel.
    int b = pBase / HW, hwB = pBase % HW;
#pragma unroll
    for (int mt = 0; mt < 4; mt++) {
        int o = oBase + wm * 64 + mt * 16 + (lane >> 2);
        float bias0 = bconv[o], bias8 = bconv[o + 8];
        float* r0p = out + ((size_t)b * CHO + o) * HW + hwB;
        float* r8p = r0p + 8 * HW;
        float sA = 0.f, qA = 0.f, sB2 = 0.f, qB = 0.f;
#pragma unroll
        for (int nt = 0; nt < 4; nt++) {
            int p = wn * 32 + nt * 8 + (lane & 3) * 2;
            float v0 = c[mt * 4 + nt][0] + bias0;
            float v1 = c[mt * 4 + nt][1] + bias0;
            float v2 = c[mt * 4 + nt][2] + bias8;
            float v3 = c[mt * 4 + nt][3] + bias8;
            *(float2*)(r0p + p) = make_float2(v0, v1);
            *(float2*)(r8p + p) = make_float2(v2, v3);
            sA  += v0 + v1;        qA += v0 * v0 + v1 * v1;
            sB2 += v2 + v3;        qB += v2 * v2 + v3 * v3;
        }
#pragma unroll
        for (int d = 1; d < 4; d <<= 1) {
            sA  += __shfl_xor_sync(0xffffffffu, sA,  d);
            qA  += __shfl_xor_sync(0xffffffffu, qA,  d);
            sB2 += __shfl_xor_sync(0xffffffffu, sB2, d);
            qB  += __shfl_xor_sync(0xffffffffu, qB,  d);
        }
        if ((lane & 3) == 0) {
            atomicAdd(&g_sums[o],           sA);
            atomicAdd(&g_sums[CHO + o],     qA);
            atomicAdd(&g_sums[o + 8],       sB2);
            atomicAdd(&g_sums[CHO + o + 8], qB);
        }
    }
}

// ---------------------------------------------------------------------------
// Kernel 5: finalize BN per-channel scale/shift from partial sums (1 block).
// ---------------------------------------------------------------------------
__global__ void __launch_bounds__(256) k_bnfin(
    const float* __restrict__ gamma,
    const float* __restrict__ beta)
{
    int o = threadIdx.x;
    float inv_n = 1.f / (float)(Bn * HW);
    float mean = g_sums[o] * inv_n;
    float var  = g_sums[CHO + o] * inv_n - mean * mean;
    float scale = gamma[o] * rsqrtf(var + BN_EPS);
    g_stats[o]       = scale;
    g_stats[CHO + o] = beta[o] - mean * scale;
}

// ---------------------------------------------------------------------------
// Kernel 6: in-place BN apply + ReLU.
// ---------------------------------------------------------------------------
__global__ void __launch_bounds__(256) k_bnapply(float* __restrict__ out)
{
    int i = blockIdx.x * 256 + threadIdx.x;
    int o = (i / HW) & (CHO - 1);
    float y = out[i] * g_stats[o] + g_stats[CHO + o];
    out[i] = fmaxf(y, 0.f);
}

// ---------------------------------------------------------------------------
extern "C" void kernel_launch(void* const* d_in, const int* in_sizes, int n_in,
                              void* d_out, int out_size)
{
    const float* x      = (const float*)d_in[0];
    const float* w_off  = (const float*)d_in[1];
    const float* b_off  = (const float*)d_in[2];
    const float* w_conv = (const float*)d_in[3];
    const float* b_conv = (const float*)d_in[4];
    const float* gamma  = (const float*)d_in[5];
    const float* beta   = (const float*)d_in[6];
    float* out = (float*)d_out;

    cudaFuncSetAttribute(k_gemm, cudaFuncAttributeMaxDynamicSharedMemorySize,
                         SMEMSZ);

    k_offset<<<Mpx / 256, 256>>>(x, w_off, b_off);
    k_wsplit<<<(CHO * KD) / 256, 256>>>(w_conv);

    dim3 gcols(Mpx / 256, CHI / 8);
    k_cols<<<gcols, 256>>>(x);

    dim3 ggemm(Mpx / 128, CHO / 128);
    k_gemm<<<ggemm, 256, SMEMSZ>>>(b_conv, out);

    k_bnfin<<<1, 256>>>(gamma, beta);
    k_bnapply<<<(size_t)Bn * CHO * HW / 256, 256>>>(out);
}

// round 14
// speedup vs baseline: 1.3795x; 1.3795x over previous
#include <cuda_runtime.h>
#include <cuda_fp16.h>

// Problem constants
#define Bn   4
#define CHI  256
#define CHO  256
#define Hd   96
#define Wd   96
#define Kt   9
#define HW   (Hd*Wd)          // 9216
#define Mpx  (Bn*HW)          // 36864
#define KD   (CHI*Kt)         // 2304
#define BN_EPS 1e-5f

// Bilinear tap: 4 clamped offsets + 4 corner weights (validity+mask folded in)
struct __align__(16) TapParam {
    int   o00, o01, o10, o11;
    float w00, w01, w10, w11;
};

// Scratch (device globals: allocation-guard-safe)
__device__ TapParam       g_params[Bn * Kt * HW];                       // ~10.6 MB
__device__ __align__(16) unsigned short g_cols[(size_t)Mpx * KD];       // 170 MB fp16
__device__ __align__(16) unsigned short g_wh[(size_t)CHO * KD];         // 1.18 MB
__device__ __align__(16) unsigned short g_wl[(size_t)CHO * KD];
__device__ __align__(16) float g_part[2 * (size_t)Mpx * 28];            // 8.3 MB
__device__ float          g_sums[2 * CHO];                              // s, s2 partials
__device__ float          g_stats[2 * CHO];                             // scale, shift

// ---------------------------------------------------------------------------
// Kernel 1: offset conv partials (half the channels per block, 2 px/thread).
// grid (Mpx/256, 2), block 128. Weights staged in smem, read as float4.
// ---------------------------------------------------------------------------
#define OC  27
#define OCP 32

__global__ void __launch_bounds__(128) k_offset(
    const float* __restrict__ x,
    const float* __restrict__ w_off)
{
    __shared__ float ws[32 * 9 * OCP];
    int p0 = blockIdx.x * 256 + threadIdx.x;       // grid.x = 144
    int b  = (blockIdx.x * 256) / HW;              // whole block in one image
    int cbase = blockIdx.y * 128;                  // channel half

    int hw0 = p0 % HW, h0 = hw0 / Wd, w0 = hw0 % Wd;
    int hw1 = (p0 + 128) % HW, h1 = hw1 / Wd, w1 = hw1 % Wd;

    float acc[2][28];
#pragma unroll
    for (int q = 0; q < 2; q++)
#pragma unroll
        for (int i = 0; i < 28; i++) acc[q][i] = 0.f;

    for (int cq = 0; cq < 4; cq++) {
        int c0 = cbase + cq * 32;
        __syncthreads();
        for (int i = threadIdx.x; i < 32 * 9 * OC; i += 128) {
            int oc = i % OC;
            int ct = i / OC;
            ws[ct * OCP + oc] = w_off[(oc * CHI + c0 + ct / 9) * 9 + (ct % 9)];
        }
        __syncthreads();

        const float* xb = x + ((size_t)b * CHI + c0) * HW;
        for (int cc = 0; cc < 32; cc++) {
            const float* xc = xb + cc * HW;
            float xv0[9], xv1[9];
#pragma unroll
            for (int ty = 0; ty < 3; ty++) {
                int ya = h0 + ty - 1, yb2 = h1 + ty - 1;
                bool yva = ((unsigned)ya < (unsigned)Hd);
                bool yvb = ((unsigned)yb2 < (unsigned)Hd);
#pragma unroll
                for (int tx = 0; tx < 3; tx++) {
                    int xa = w0 + tx - 1, xb2 = w1 + tx - 1;
                    xv0[ty * 3 + tx] = (yva && (unsigned)xa < (unsigned)Wd)
                                     ? xc[ya * Wd + xa] : 0.f;
                    xv1[ty * 3 + tx] = (yvb && (unsigned)xb2 < (unsigned)Wd)
                                     ? xc[yb2 * Wd + xb2] : 0.f;
                }
            }
#pragma unroll
            for (int t = 0; t < 9; t++) {
                const float4* wr4 = (const float4*)&ws[(cc * 9 + t) * OCP];
                float v0 = xv0[t], v1 = xv1[t];
#pragma unroll
                for (int j = 0; j < 7; j++) {
                    float4 w4 = wr4[j];
                    acc[0][j*4+0] += w4.x * v0;  acc[1][j*4+0] += w4.x * v1;
                    acc[0][j*4+1] += w4.y * v0;  acc[1][j*4+1] += w4.y * v1;
                    acc[0][j*4+2] += w4.z * v0;  acc[1][j*4+2] += w4.z * v1;
                    acc[0][j*4+3] += w4.w * v0;  acc[1][j*4+3] += w4.w * v1;
                }
            }
        }
    }

#pragma unroll
    for (int q = 0; q < 2; q++) {
        int p = p0 + q * 128;
        float4* dst = (float4*)(g_part + ((size_t)blockIdx.y * Mpx + p) * 28);
#pragma unroll
        for (int j = 0; j < 7; j++)
            dst[j] = make_float4(acc[q][4*j], acc[q][4*j+1],
                                 acc[q][4*j+2], acc[q][4*j+3]);
    }
}

// ---------------------------------------------------------------------------
// Kernel 1b: combine channel-half partials + bias -> TapParams.
// ---------------------------------------------------------------------------
__global__ void __launch_bounds__(256) k_taps(const float* __restrict__ b_off)
{
    int p  = blockIdx.x * 256 + threadIdx.x;
    int b  = p / HW, hw = p % HW;
    int h  = hw / Wd, w = hw % Wd;

    float acc[28];
    const float4* a0 = (const float4*)(g_part + (size_t)p * 28);
    const float4* a1 = (const float4*)(g_part + ((size_t)Mpx + p) * 28);
#pragma unroll
    for (int j = 0; j < 7; j++) {
        float4 u = a0[j], v = a1[j];
        acc[4*j+0] = u.x + v.x;  acc[4*j+1] = u.y + v.y;
        acc[4*j+2] = u.z + v.z;  acc[4*j+3] = u.w + v.w;
    }

#pragma unroll
    for (int k = 0; k < Kt; k++) {
        float dy = acc[2 * k]     + b_off[2 * k];
        float dx = acc[2 * k + 1] + b_off[2 * k + 1];
        float mz = acc[18 + k]    + b_off[18 + k];
        float m  = 1.f / (1.f + expf(-mz));

        float py = dy + (float)(h + k / 3 - 1);
        float px = dx + (float)(w + k % 3 - 1);
        float fy = floorf(py), fx = floorf(px);
        float ly = py - fy,    lx = px - fx;
        int y0 = (int)fy, x0 = (int)fx, y1 = y0 + 1, x1 = x0 + 1;

        float vy0 = ((unsigned)y0 < (unsigned)Hd) ? 1.f : 0.f;
        float vy1 = ((unsigned)y1 < (unsigned)Hd) ? 1.f : 0.f;
        float vx0 = ((unsigned)x0 < (unsigned)Wd) ? 1.f : 0.f;
        float vx1 = ((unsigned)x1 < (unsigned)Wd) ? 1.f : 0.f;

        int y0c = min(max(y0, 0), Hd - 1), y1c = min(max(y1, 0), Hd - 1);
        int x0c = min(max(x0, 0), Wd - 1), x1c = min(max(x1, 0), Wd - 1);

        TapParam tp;
        tp.o00 = y0c * Wd + x0c;  tp.o01 = y0c * Wd + x1c;
        tp.o10 = y1c * Wd + x0c;  tp.o11 = y1c * Wd + x1c;
        tp.w00 = (1.f - ly) * (1.f - lx) * vy0 * vx0 * m;
        tp.w01 = (1.f - ly) * lx         * vy0 * vx1 * m;
        tp.w10 = ly * (1.f - lx)         * vy1 * vx0 * m;
        tp.w11 = ly * lx                 * vy1 * vx1 * m;
        g_params[(b * Kt + k) * HW + hw] = tp;
    }
}

// ---------------------------------------------------------------------------
// Kernel 2: split w_conv into fp16 hi/lo, [CHO][KD] K-major.
// Block 0 also zeros ALL 512 g_sums entries (2 per thread).
// ---------------------------------------------------------------------------
__global__ void __launch_bounds__(256) k_wsplit(const float* __restrict__ w)
{
    int i = blockIdx.x * 256 + threadIdx.x;
    if (blockIdx.x == 0) {
        g_sums[threadIdx.x]       = 0.f;
        g_sums[threadIdx.x + 256] = 0.f;
    }
    float v = w[i];
    __half hh = __float2half_rn(v);
    float r = v - __half2float(hh);
    __half hl = __float2half_rn(r);
    g_wh[i] = __half_as_ushort(hh);
    g_wl[i] = __half_as_ushort(hl);
}

// ---------------------------------------------------------------------------
// Kernel 3: deformable im2col -> fp16, K-major [pixel][KD].
// Thread = (pixel, 8-channel chunk): wide parallelism.
// ---------------------------------------------------------------------------
__global__ void __launch_bounds__(256) k_cols(const float* __restrict__ x)
{
    int p  = blockIdx.x * 256 + threadIdx.x;   // grid.x = 144
    int c0 = blockIdx.y * 8;                   // grid.y = 32
    int b  = p / HW, hw = p % HW;
    const float* xb = x + ((size_t)b * CHI + c0) * HW;

    unsigned buf[36];
#pragma unroll
    for (int j = 0; j < 36; j++) buf[j] = 0u;

#pragma unroll
    for (int k = 0; k < Kt; k++) {
        TapParam tp = g_params[(b * Kt + k) * HW + hw];
#pragma unroll
        for (int cc = 0; cc < 8; cc++) {
            const float* xc = xb + cc * HW;
            float v = tp.w00 * __ldg(xc + tp.o00) + tp.w01 * __ldg(xc + tp.o01)
                    + tp.w10 * __ldg(xc + tp.o10) + tp.w11 * __ldg(xc + tp.o11);
            unsigned hb = (unsigned)__half_as_ushort(__float2half_rn(v));
            int e = cc * 9 + k;
            buf[e >> 1] |= hb << ((e & 1) * 16);
        }
    }

    uint4* dh = (uint4*)(g_cols + (size_t)p * KD + c0 * 9);
#pragma unroll
    for (int j = 0; j < 9; j++)
        dh[j] = make_uint4(buf[4*j], buf[4*j+1], buf[4*j+2], buf[4*j+3]);
}

// ---------------------------------------------------------------------------
// Kernel 4: mma.sync fp16 GEMM, split-A 2-product fp32 accumulation.
// CTA: 128 CHO x 128 pixels. 8 warps, warp tile 64x32. BK=64, 3-stage cp.async.
// Single __syncthreads per chunk. Epilogue: bias, NCHW store, BN partial sums.
// ---------------------------------------------------------------------------
#define NCHUNK 36
#define TILEB  16384                 // 128 rows x 128 bytes
#define STAGEB (3 * TILEB)           // Ahi Alo B
#define NSTAGE 3
#define SMEMSZ (NSTAGE * STAGEB)     // 147456

#define LDM4(R0,R1,R2,R3,ADDR) \
    asm volatile("ldmatrix.sync.aligned.m8n8.x4.shared.b16 {%0,%1,%2,%3}, [%4];" \
                 : "=r"(R0),"=r"(R1),"=r"(R2),"=r"(R3) : "r"(ADDR))

#define MMA(C,A,B0,B1) \
    asm volatile("mma.sync.aligned.m16n8k16.row.col.f32.f16.f16.f32 " \
                 "{%0,%1,%2,%3},{%4,%5,%6,%7},{%8,%9},{%0,%1,%2,%3};" \
                 : "+f"((C)[0]),"+f"((C)[1]),"+f"((C)[2]),"+f"((C)[3]) \
                 : "r"((A)[0]),"r"((A)[1]),"r"((A)[2]),"r"((A)[3]),   \
                   "r"(B0),"r"(B1))

__device__ __forceinline__ void load_chunk(unsigned smBase, int stage, int chunk,
                                           int oBase, int pBase, int tid)
{
    unsigned dstBase = smBase + stage * STAGEB;
    int k0 = chunk * 64;
#pragma unroll
    for (int j = 0; j < 12; j++) {
        int i    = tid + j * 256;        // 0..3071
        int tile = i >> 10;              // 0..2
        int row  = (i >> 3) & 127;
        int u    = i & 7;
        const unsigned short* src;
        int rbase;
        if (tile == 0)      { src = g_wh;   rbase = oBase; }
        else if (tile == 1) { src = g_wl;   rbase = oBase; }
        else                { src = g_cols; rbase = pBase; }
        const char* g = (const char*)src + ((size_t)(rbase + row) * KD + k0) * 2 + u * 16;
        unsigned d = dstBase + tile * TILEB + row * 128 + ((u ^ (row & 7)) * 16);
        asm volatile("cp.async.cg.shared.global [%0], [%1], 16;" :: "r"(d), "l"(g));
    }
    asm volatile("cp.async.commit_group;" ::: "memory");
}

__global__ void __launch_bounds__(256, 1) k_gemm(
    const float* __restrict__ bconv,
    float* __restrict__ out)
{
    extern __shared__ char sm[];
    unsigned smBase = (unsigned)__cvta_generic_to_shared(sm);

    int tid = threadIdx.x, lane = tid & 31, wid = tid >> 5;
    int wm = wid & 1;            // m half (64 rows)
    int wn = wid >> 1;           // n quarter (32 pixels)
    int pBase = blockIdx.x * 128;
    int oBase = blockIdx.y * 128;

    // ldmatrix per-lane geometry
    unsigned aRL = ((lane >> 3) & 1) * 8 + (lane & 7);   // A: row-in-tile16
    unsigned aU  = lane >> 4;                            // A: k8 unit
    unsigned bRL = ((lane >> 4) & 1) * 8 + (lane & 7);   // B: row-in-tile16
    unsigned bU  = (lane >> 3) & 1;                      // B: k8 unit
    unsigned aRowOff[4], bRowOff[2];
#pragma unroll
    for (int mt = 0; mt < 4; mt++) aRowOff[mt] = (wm * 64 + mt * 16 + aRL) * 128;
#pragma unroll
    for (int nt = 0; nt < 2; nt++) bRowOff[nt] = (wn * 32 + nt * 16 + bRL) * 128;
    unsigned aMsk = aRL & 7, bMsk = bRL & 7;

    float c[16][4];
#pragma unroll
    for (int i = 0; i < 16; i++)
#pragma unroll
        for (int j = 0; j < 4; j++) c[i][j] = 0.f;

    load_chunk(smBase, 0, 0, oBase, pBase, tid);
    load_chunk(smBase, 1, 1, oBase, pBase, tid);

    for (int ch = 0; ch < NCHUNK; ch++) {
        int st = ch % NSTAGE;
        if (ch + 1 < NCHUNK) {
            asm volatile("cp.async.wait_group 1;" ::: "memory");
        } else {
            asm volatile("cp.async.wait_group 0;" ::: "memory");
        }
        __syncthreads();
        if (ch + 2 < NCHUNK)
            load_chunk(smBase, (ch + 2) % NSTAGE, ch + 2, oBase, pBase, tid);

        unsigned base = smBase + st * STAGEB;
        unsigned sAh = base, sAl = base + TILEB, sB = base + 2 * TILEB;

#pragma unroll
        for (int kk = 0; kk < 4; kk++) {
            unsigned ua = ((kk * 2 + aU) ^ aMsk) * 16;
            unsigned ub = ((kk * 2 + bU) ^ bMsk) * 16;

            unsigned ah[4][4], al[4][4], bh[2][4];
#pragma unroll
            for (int mt = 0; mt < 4; mt++) {
                LDM4(ah[mt][0], ah[mt][1], ah[mt][2], ah[mt][3], sAh + aRowOff[mt] + ua);
                LDM4(al[mt][0], al[mt][1], al[mt][2], al[mt][3], sAl + aRowOff[mt] + ua);
            }
#pragma unroll
            for (int nt = 0; nt < 2; nt++)
                LDM4(bh[nt][0], bh[nt][1], bh[nt][2], bh[nt][3], sB + bRowOff[nt] + ub);

#pragma unroll
            for (int mt = 0; mt < 4; mt++)
#pragma unroll
                for (int nt = 0; nt < 4; nt++) {
                    int n2 = nt >> 1, jj = (nt & 1) * 2;
                    float* cc = c[mt * 4 + nt];
                    MMA(cc, ah[mt], bh[n2][jj], bh[n2][jj + 1]);
                    MMA(cc, al[mt], bh[n2][jj], bh[n2][jj + 1]);
                }
        }
        __syncthreads();
    }

    // Epilogue: + bias, NCHW stores, BN partial sums (s, s2) per channel.
    int b = pBase / HW, hwB = pBase % HW;
#pragma unroll
    for (int mt = 0; mt < 4; mt++) {
        int o = oBase + wm * 64 + mt * 16 + (lane >> 2);
        float bias0 = bconv[o], bias8 = bconv[o + 8];
        float* r0p = out + ((size_t)b * CHO + o) * HW + hwB;
        float* r8p = r0p + 8 * HW;
        float sA = 0.f, qA = 0.f, sB2 = 0.f, qB = 0.f;
#pragma unroll
        for (int nt = 0; nt < 4; nt++) {
            int p = wn * 32 + nt * 8 + (lane & 3) * 2;
            float v0 = c[mt * 4 + nt][0] + bias0;
            float v1 = c[mt * 4 + nt][1] + bias0;
            float v2 = c[mt * 4 + nt][2] + bias8;
            float v3 = c[mt * 4 + nt][3] + bias8;
            *(float2*)(r0p + p) = make_float2(v0, v1);
            *(float2*)(r8p + p) = make_float2(v2, v3);
            sA  += v0 + v1;        qA += v0 * v0 + v1 * v1;
            sB2 += v2 + v3;        qB += v2 * v2 + v3 * v3;
        }
#pragma unroll
        for (int d = 1; d < 4; d <<= 1) {
            sA  += __shfl_xor_sync(0xffffffffu, sA,  d);
            qA  += __shfl_xor_sync(0xffffffffu, qA,  d);
            sB2 += __shfl_xor_sync(0xffffffffu, sB2, d);
            qB  += __shfl_xor_sync(0xffffffffu, qB,  d);
        }
        if ((lane & 3) == 0) {
            atomicAdd(&g_sums[o],           sA);
            atomicAdd(&g_sums[CHO + o],     qA);
            atomicAdd(&g_sums[o + 8],       sB2);
            atomicAdd(&g_sums[CHO + o + 8], qB);
        }
    }
}

// ---------------------------------------------------------------------------
// Kernel 5: finalize BN per-channel scale/shift from partial sums (1 block).
// ---------------------------------------------------------------------------
__global__ void __launch_bounds__(256) k_bnfin(
    const float* __restrict__ gamma,
    const float* __restrict__ beta)
{
    int o = threadIdx.x;
    float inv_n = 1.f / (float)(Bn * HW);
    float mean = g_sums[o] * inv_n;
    float var  = g_sums[CHO + o] * inv_n - mean * mean;
    float scale = gamma[o] * rsqrtf(var + BN_EPS);
    g_stats[o]       = scale;
    g_stats[CHO + o] = beta[o] - mean * scale;
}

// ---------------------------------------------------------------------------
// Kernel 6: in-place BN apply + ReLU.
// ---------------------------------------------------------------------------
__global__ void __launch_bounds__(256) k_bnapply(float* __restrict__ out)
{
    int i = blockIdx.x * 256 + threadIdx.x;
    int o = (i / HW) & (CHO - 1);
    float y = out[i] * g_stats[o] + g_stats[CHO + o];
    out[i] = fmaxf(y, 0.f);
}

// ---------------------------------------------------------------------------
extern "C" void kernel_launch(void* const* d_in, const int* in_sizes, int n_in,
                              void* d_out, int out_size)
{
    const float* x      = (const float*)d_in[0];
    const float* w_off  = (const float*)d_in[1];
    const float* b_off  = (const float*)d_in[2];
    const float* w_conv = (const float*)d_in[3];
    const float* b_conv = (const float*)d_in[4];
    const float* gamma  = (const float*)d_in[5];
    const float* beta   = (const float*)d_in[6];
    float* out = (float*)d_out;

    cudaFuncSetAttribute(k_gemm, cudaFuncAttributeMaxDynamicSharedMemorySize,
                         SMEMSZ);

    dim3 goff(Mpx / 256, 2);
    k_offset<<<goff, 128>>>(x, w_off);
    k_taps<<<Mpx / 256, 256>>>(b_off);
    k_wsplit<<<(CHO * KD) / 256, 256>>>(w_conv);

    dim3 gcols(Mpx / 256, CHI / 8);
    k_cols<<<gcols, 256>>>(x);

    dim3 ggemm(Mpx / 128, CHO / 128);
    k_gemm<<<ggemm, 256, SMEMSZ>>>(b_conv, out);

    k_bnfin<<<1, 256>>>(gamma, beta);
    k_bnapply<<<(size_t)Bn * CHO * HW / 256, 256>>>(out);
}

// round 16
// speedup vs baseline: 1.6073x; 1.1651x over previous
#include <cuda_runtime.h>
#include <cuda_fp16.h>

// Problem constants
#define Bn   4
#define CHI  256
#define CHO  256
#define Hd   96
#define Wd   96
#define Kt   9
#define HW   (Hd*Wd)          // 9216
#define Mpx  (Bn*HW)          // 36864
#define KD   (CHI*Kt)         // 2304
#define BN_EPS 1e-5f

// Scratch (device globals: allocation-guard-safe)
__device__ __align__(16) unsigned short g_cols[(size_t)Mpx * KD];       // 170 MB fp16
__device__ __align__(16) unsigned short g_wh[(size_t)CHO * KD];         // 1.18 MB
__device__ __align__(16) float g_part[4 * (size_t)Mpx * 28];            // 16.5 MB
__device__ __align__(8)  uint2  g_po[Bn * Kt * HW];                     // packed offsets
__device__ __align__(16) float4 g_pw[Bn * Kt * HW];                     // corner weights
__device__ float          g_sums[2 * CHO];                              // s, s2 partials
__device__ float          g_stats[2 * CHO];                             // scale, shift

// ---------------------------------------------------------------------------
// Kernel 1: offset conv partials (quarter channels per block, 2 px/thread).
// grid (Mpx/256, 4), block 128. Weights staged in smem, read as float4.
// ---------------------------------------------------------------------------
#define OC  27
#define OCP 32

__global__ void __launch_bounds__(128) k_offset(
    const float* __restrict__ x,
    const float* __restrict__ w_off)
{
    __shared__ float ws[32 * 9 * OCP];
    int p0 = blockIdx.x * 256 + threadIdx.x;       // grid.x = 144
    int b  = (blockIdx.x * 256) / HW;              // whole block in one image
    int cbase = blockIdx.y * 64;                   // channel quarter

    int hw0 = p0 % HW, h0 = hw0 / Wd, w0 = hw0 % Wd;
    int hw1 = (p0 + 128) % HW, h1 = hw1 / Wd, w1 = hw1 % Wd;

    float acc[2][28];
#pragma unroll
    for (int q = 0; q < 2; q++)
#pragma unroll
        for (int i = 0; i < 28; i++) acc[q][i] = 0.f;

    for (int cq = 0; cq < 2; cq++) {
        int c0 = cbase + cq * 32;
        __syncthreads();
        for (int i = threadIdx.x; i < 32 * 9 * OC; i += 128) {
            int oc = i % OC;
            int ct = i / OC;
            ws[ct * OCP + oc] = w_off[(oc * CHI + c0 + ct / 9) * 9 + (ct % 9)];
        }
        __syncthreads();

        const float* xb = x + ((size_t)b * CHI + c0) * HW;
        for (int cc = 0; cc < 32; cc++) {
            const float* xc = xb + cc * HW;
            float xv0[9], xv1[9];
#pragma unroll
            for (int ty = 0; ty < 3; ty++) {
                int ya = h0 + ty - 1, yb2 = h1 + ty - 1;
                bool yva = ((unsigned)ya < (unsigned)Hd);
                bool yvb = ((unsigned)yb2 < (unsigned)Hd);
#pragma unroll
                for (int tx = 0; tx < 3; tx++) {
                    int xa = w0 + tx - 1, xb2 = w1 + tx - 1;
                    xv0[ty * 3 + tx] = (yva && (unsigned)xa < (unsigned)Wd)
                                     ? xc[ya * Wd + xa] : 0.f;
                    xv1[ty * 3 + tx] = (yvb && (unsigned)xb2 < (unsigned)Wd)
                                     ? xc[yb2 * Wd + xb2] : 0.f;
                }
            }
#pragma unroll
            for (int t = 0; t < 9; t++) {
                const float4* wr4 = (const float4*)&ws[(cc * 9 + t) * OCP];
                float v0 = xv0[t], v1 = xv1[t];
#pragma unroll
                for (int j = 0; j < 7; j++) {
                    float4 w4 = wr4[j];
                    acc[0][j*4+0] += w4.x * v0;  acc[1][j*4+0] += w4.x * v1;
                    acc[0][j*4+1] += w4.y * v0;  acc[1][j*4+1] += w4.y * v1;
                    acc[0][j*4+2] += w4.z * v0;  acc[1][j*4+2] += w4.z * v1;
                    acc[0][j*4+3] += w4.w * v0;  acc[1][j*4+3] += w4.w * v1;
                }
            }
        }
    }

#pragma unroll
    for (int q = 0; q < 2; q++) {
        int p = p0 + q * 128;
        float4* dst = (float4*)(g_part + ((size_t)blockIdx.y * Mpx + p) * 28);
#pragma unroll
        for (int j = 0; j < 7; j++)
            dst[j] = make_float4(acc[q][4*j], acc[q][4*j+1],
                                 acc[q][4*j+2], acc[q][4*j+3]);
    }
}

// ---------------------------------------------------------------------------
// Kernel 1b: combine 4 channel-quarter partials + bias -> packed tap params.
// ---------------------------------------------------------------------------
__global__ void __launch_bounds__(256) k_taps(const float* __restrict__ b_off)
{
    int p  = blockIdx.x * 256 + threadIdx.x;
    int b  = p / HW, hw = p % HW;
    int h  = hw / Wd, w = hw % Wd;

    float acc[28];
#pragma unroll
    for (int j = 0; j < 7; j++) {
        float4 s = make_float4(0.f, 0.f, 0.f, 0.f);
#pragma unroll
        for (int q = 0; q < 4; q++) {
            float4 u = ((const float4*)(g_part + ((size_t)q * Mpx + p) * 28))[j];
            s.x += u.x; s.y += u.y; s.z += u.z; s.w += u.w;
        }
        acc[4*j+0] = s.x;  acc[4*j+1] = s.y;
        acc[4*j+2] = s.z;  acc[4*j+3] = s.w;
    }

#pragma unroll
    for (int k = 0; k < Kt; k++) {
        float dy = acc[2 * k]     + b_off[2 * k];
        float dx = acc[2 * k + 1] + b_off[2 * k + 1];
        float mz = acc[18 + k]    + b_off[18 + k];
        float m  = 1.f / (1.f + expf(-mz));

        float py = dy + (float)(h + k / 3 - 1);
        float px = dx + (float)(w + k % 3 - 1);
        float fy = floorf(py), fx = floorf(px);
        float ly = py - fy,    lx = px - fx;
        int y0 = (int)fy, x0 = (int)fx, y1 = y0 + 1, x1 = x0 + 1;

        float vy0 = ((unsigned)y0 < (unsigned)Hd) ? 1.f : 0.f;
        float vy1 = ((unsigned)y1 < (unsigned)Hd) ? 1.f : 0.f;
        float vx0 = ((unsigned)x0 < (unsigned)Wd) ? 1.f : 0.f;
        float vx1 = ((unsigned)x1 < (unsigned)Wd) ? 1.f : 0.f;

        int y0c = min(max(y0, 0), Hd - 1), y1c = min(max(y1, 0), Hd - 1);
        int x0c = min(max(x0, 0), Wd - 1), x1c = min(max(x1, 0), Wd - 1);

        unsigned o00 = (unsigned)(y0c * Wd + x0c);
        unsigned o01 = (unsigned)(y0c * Wd + x1c);
        unsigned o10 = (unsigned)(y1c * Wd + x0c);
        unsigned o11 = (unsigned)(y1c * Wd + x1c);

        int idx = (b * Kt + k) * HW + hw;
        g_po[idx] = make_uint2(o00 | (o01 << 16), o10 | (o11 << 16));
        g_pw[idx] = make_float4(
            (1.f - ly) * (1.f - lx) * vy0 * vx0 * m,
            (1.f - ly) * lx         * vy0 * vx1 * m,
            ly * (1.f - lx)         * vy1 * vx0 * m,
            ly * lx                 * vy1 * vx1 * m);
    }
}

// ---------------------------------------------------------------------------
// Kernel 2: w_conv -> fp16, [CHO][KD] K-major. Block 0 zeros all 512 g_sums.
// ---------------------------------------------------------------------------
__global__ void __launch_bounds__(256) k_wsplit(const float* __restrict__ w)
{
    int i = blockIdx.x * 256 + threadIdx.x;
    if (blockIdx.x == 0) {
        g_sums[threadIdx.x]       = 0.f;
        g_sums[threadIdx.x + 256] = 0.f;
    }
    g_wh[i] = __half_as_ushort(__float2half_rn(w[i]));
}

// ---------------------------------------------------------------------------
// Kernel 3: deformable im2col -> fp16, K-major [pixel][KD].
// Thread = (pixel, 8-channel chunk); packed 24B params.
// ---------------------------------------------------------------------------
__global__ void __launch_bounds__(256) k_cols(const float* __restrict__ x)
{
    int p  = blockIdx.x * 256 + threadIdx.x;   // grid.x = 144
    int c0 = blockIdx.y * 8;                   // grid.y = 32
    int b  = p / HW, hw = p % HW;
    const float* xb = x + ((size_t)b * CHI + c0) * HW;

    unsigned buf[36];
#pragma unroll
    for (int j = 0; j < 36; j++) buf[j] = 0u;

#pragma unroll
    for (int k = 0; k < Kt; k++) {
        int idx = (b * Kt + k) * HW + hw;
        uint2  po = __ldg(&g_po[idx]);
        float4 pw = __ldg(&g_pw[idx]);
        int o00 = po.x & 0xffff, o01 = po.x >> 16;
        int o10 = po.y & 0xffff, o11 = po.y >> 16;
#pragma unroll
        for (int cc = 0; cc < 8; cc++) {
            const float* xc = xb + cc * HW;
            float v = pw.x * __ldg(xc + o00) + pw.y * __ldg(xc + o01)
                    + pw.z * __ldg(xc + o10) + pw.w * __ldg(xc + o11);
            unsigned hb = (unsigned)__half_as_ushort(__float2half_rn(v));
            int e = cc * 9 + k;
            buf[e >> 1] |= hb << ((e & 1) * 16);
        }
    }

    uint4* dh = (uint4*)(g_cols + (size_t)p * KD + c0 * 9);
#pragma unroll
    for (int j = 0; j < 9; j++)
        dh[j] = make_uint4(buf[4*j], buf[4*j+1], buf[4*j+2], buf[4*j+3]);
}

// ---------------------------------------------------------------------------
// Kernel 4: mma.sync fp16 GEMM, single-product fp32 accumulation.
// CTA: 128 CHO x 128 pixels. 8 warps, warp tile 64x32. BK=64, 4-stage cp.async.
// Epilogue: bias, NCHW store, BN partial sums.
// ---------------------------------------------------------------------------
#define NCHUNK 36
#define TILEB  16384                 // 128 rows x 128 bytes
#define STAGEB (2 * TILEB)           // A B
#define NSTAGE 4
#define SMEMSZ (NSTAGE * STAGEB)     // 131072

#define LDM4(R0,R1,R2,R3,ADDR) \
    asm volatile("ldmatrix.sync.aligned.m8n8.x4.shared.b16 {%0,%1,%2,%3}, [%4];" \
                 : "=r"(R0),"=r"(R1),"=r"(R2),"=r"(R3) : "r"(ADDR))

#define MMA(C,A,B0,B1) \
    asm volatile("mma.sync.aligned.m16n8k16.row.col.f32.f16.f16.f32 " \
                 "{%0,%1,%2,%3},{%4,%5,%6,%7},{%8,%9},{%0,%1,%2,%3};" \
                 : "+f"((C)[0]),"+f"((C)[1]),"+f"((C)[2]),"+f"((C)[3]) \
                 : "r"((A)[0]),"r"((A)[1]),"r"((A)[2]),"r"((A)[3]),   \
                   "r"(B0),"r"(B1))

__device__ __forceinline__ void load_chunk(unsigned smBase, int stage, int chunk,
                                           int oBase, int pBase, int tid)
{
    unsigned dstBase = smBase + stage * STAGEB;
    int k0 = chunk * 64;
#pragma unroll
    for (int j = 0; j < 8; j++) {
        int i    = tid + j * 256;        // 0..2047
        int tile = i >> 10;              // 0..1
        int row  = (i >> 3) & 127;
        int u    = i & 7;
        const unsigned short* src = tile ? g_cols : g_wh;
        int rbase = tile ? pBase : oBase;
        const char* g = (const char*)src + ((size_t)(rbase + row) * KD + k0) * 2 + u * 16;
        unsigned d = dstBase + tile * TILEB + row * 128 + ((u ^ (row & 7)) * 16);
        asm volatile("cp.async.cg.shared.global [%0], [%1], 16;" :: "r"(d), "l"(g));
    }
    asm volatile("cp.async.commit_group;" ::: "memory");
}

__global__ void __launch_bounds__(256, 1) k_gemm(
    const float* __restrict__ bconv,
    float* __restrict__ out)
{
    extern __shared__ char sm[];
    unsigned smBase = (unsigned)__cvta_generic_to_shared(sm);

    int tid = threadIdx.x, lane = tid & 31, wid = tid >> 5;
    int wm = wid & 1;            // m half (64 rows)
    int wn = wid >> 1;           // n quarter (32 pixels)
    int pBase = blockIdx.x * 128;
    int oBase = blockIdx.y * 128;

    // ldmatrix per-lane geometry
    unsigned aRL = ((lane >> 3) & 1) * 8 + (lane & 7);   // A: row-in-tile16
    unsigned aU  = lane >> 4;                            // A: k8 unit
    unsigned bRL = ((lane >> 4) & 1) * 8 + (lane & 7);   // B: row-in-tile16
    unsigned bU  = (lane >> 3) & 1;                      // B: k8 unit
    unsigned aRowOff[4], bRowOff[2];
#pragma unroll
    for (int mt = 0; mt < 4; mt++) aRowOff[mt] = (wm * 64 + mt * 16 + aRL) * 128;
#pragma unroll
    for (int nt = 0; nt < 2; nt++) bRowOff[nt] = (wn * 32 + nt * 16 + bRL) * 128;
    unsigned aMsk = aRL & 7, bMsk = bRL & 7;

    float c[16][4];
#pragma unroll
    for (int i = 0; i < 16; i++)
#pragma unroll
        for (int j = 0; j < 4; j++) c[i][j] = 0.f;

    load_chunk(smBase, 0, 0, oBase, pBase, tid);
    load_chunk(smBase, 1, 1, oBase, pBase, tid);
    load_chunk(smBase, 2, 2, oBase, pBase, tid);

    for (int ch = 0; ch < NCHUNK; ch++) {
        int st = ch % NSTAGE;
        if (ch + 2 < NCHUNK) {
            asm volatile("cp.async.wait_group 2;" ::: "memory");
        } else if (ch + 1 < NCHUNK) {
            asm volatile("cp.async.wait_group 1;" ::: "memory");
        } else {
            asm volatile("cp.async.wait_group 0;" ::: "memory");
        }
        __syncthreads();
        if (ch + 3 < NCHUNK)
            load_chunk(smBase, (ch + 3) % NSTAGE, ch + 3, oBase, pBase, tid);

        unsigned base = smBase + st * STAGEB;
        unsigned sA = base, sB = base + TILEB;

#pragma unroll
        for (int kk = 0; kk < 4; kk++) {
            unsigned ua = ((kk * 2 + aU) ^ aMsk) * 16;
            unsigned ub = ((kk * 2 + bU) ^ bMsk) * 16;

            unsigned ah[4][4], bh[2][4];
#pragma unroll
            for (int mt = 0; mt < 4; mt++)
                LDM4(ah[mt][0], ah[mt][1], ah[mt][2], ah[mt][3], sA + aRowOff[mt] + ua);
#pragma unroll
            for (int nt = 0; nt < 2; nt++)
                LDM4(bh[nt][0], bh[nt][1], bh[nt][2], bh[nt][3], sB + bRowOff[nt] + ub);

#pragma unroll
            for (int mt = 0; mt < 4; mt++)
#pragma unroll
                for (int nt = 0; nt < 4; nt++) {
                    int n2 = nt >> 1, jj = (nt & 1) * 2;
                    MMA(c[mt * 4 + nt], ah[mt], bh[n2][jj], bh[n2][jj + 1]);
                }
        }
        __syncthreads();
    }

    // Epilogue: + bias, NCHW stores, BN partial sums (s, s2) per channel.
    int b = pBase / HW, hwB = pBase % HW;
#pragma unroll
    for (int mt = 0; mt < 4; mt++) {
        int o = oBase + wm * 64 + mt * 16 + (lane >> 2);
        float bias0 = bconv[o], bias8 = bconv[o + 8];
        float* r0p = out + ((size_t)b * CHO + o) * HW + hwB;
        float* r8p = r0p + 8 * HW;
        float sA2 = 0.f, qA = 0.f, sB2 = 0.f, qB = 0.f;
#pragma unroll
        for (int nt = 0; nt < 4; nt++) {
            int p = wn * 32 + nt * 8 + (lane & 3) * 2;
            float v0 = c[mt * 4 + nt][0] + bias0;
            float v1 = c[mt * 4 + nt][1] + bias0;
            float v2 = c[mt * 4 + nt][2] + bias8;
            float v3 = c[mt * 4 + nt][3] + bias8;
            *(float2*)(r0p + p) = make_float2(v0, v1);
            *(float2*)(r8p + p) = make_float2(v2, v3);
            sA2 += v0 + v1;        qA += v0 * v0 + v1 * v1;
            sB2 += v2 + v3;        qB += v2 * v2 + v3 * v3;
        }
#pragma unroll
        for (int d = 1; d < 4; d <<= 1) {
            sA2 += __shfl_xor_sync(0xffffffffu, sA2, d);
            qA  += __shfl_xor_sync(0xffffffffu, qA,  d);
            sB2 += __shfl_xor_sync(0xffffffffu, sB2, d);
            qB  += __shfl_xor_sync(0xffffffffu, qB,  d);
        }
        if ((lane & 3) == 0) {
            atomicAdd(&g_sums[o],           sA2);
            atomicAdd(&g_sums[CHO + o],     qA);
            atomicAdd(&g_sums[o + 8],       sB2);
            atomicAdd(&g_sums[CHO + o + 8], qB);
        }
    }
}

// ---------------------------------------------------------------------------
// Kernel 5: finalize BN per-channel scale/shift from partial sums (1 block).
// ---------------------------------------------------------------------------
__global__ void __launch_bounds__(256) k_bnfin(
    const float* __restrict__ gamma,
    const float* __restrict__ beta)
{
    int o = threadIdx.x;
    float inv_n = 1.f / (float)(Bn * HW);
    float mean = g_sums[o] * inv_n;
    float var  = g_sums[CHO + o] * inv_n - mean * mean;
    float scale = gamma[o] * rsqrtf(var + BN_EPS);
    g_stats[o]       = scale;
    g_stats[CHO + o] = beta[o] - mean * scale;
}

// ---------------------------------------------------------------------------
// Kernel 6: in-place BN apply + ReLU.
// ---------------------------------------------------------------------------
__global__ void __launch_bounds__(256) k_bnapply(float* __restrict__ out)
{
    int i = blockIdx.x * 256 + threadIdx.x;
    int o = (i / HW) & (CHO - 1);
    float y = out[i] * g_stats[o] + g_stats[CHO + o];
    out[i] = fmaxf(y, 0.f);
}

// ---------------------------------------------------------------------------
extern "C" void kernel_launch(void* const* d_in, const int* in_sizes, int n_in,
                              void* d_out, int out_size)
{
    const float* x      = (const float*)d_in[0];
    const float* w_off  = (const float*)d_in[1];
    const float* b_off  = (const float*)d_in[2];
    const float* w_conv = (const float*)d_in[3];
    const float* b_conv = (const float*)d_in[4];
    const float* gamma  = (const float*)d_in[5];
    const float* beta   = (const float*)d_in[6];
    float* out = (float*)d_out;

    cudaFuncSetAttribute(k_gemm, cudaFuncAttributeMaxDynamicSharedMemorySize,
                         SMEMSZ);

    dim3 goff(Mpx / 256, 4);
    k_offset<<<goff, 128>>>(x, w_off);
    k_taps<<<Mpx / 256, 256>>>(b_off);
    k_wsplit<<<(CHO * KD) / 256, 256>>>(w_conv);

    dim3 gcols(Mpx / 256, CHI / 8);
    k_cols<<<gcols, 256>>>(x);

    dim3 ggemm(Mpx / 128, CHO / 128);
    k_gemm<<<ggemm, 256, SMEMSZ>>>(b_conv, out);

    k_bnfin<<<1, 256>>>(gamma, beta);
    k_bnapply<<<(size_t)Bn * CHO * HW / 256, 256>>>(out);
}

// round 17
// speedup vs baseline: 1.6796x; 1.0450x over previous
#include <cuda_runtime.h>
#include <cuda_fp16.h>

// Problem constants
#define Bn   4
#define CHI  256
#define CHO  256
#define Hd   96
#define Wd   96
#define Kt   9
#define HW   (Hd*Wd)          // 9216
#define Mpx  (Bn*HW)          // 36864
#define KD   (CHI*Kt)         // 2304
#define BN_EPS 1e-5f

typedef unsigned long long ull;

// Scratch (device globals: allocation-guard-safe)
__device__ __align__(16) unsigned short g_cols[(size_t)Mpx * KD];       // 170 MB fp16
__device__ __align__(16) unsigned short g_wh[(size_t)CHO * KD];         // 1.18 MB
__device__ __align__(16) float g_part[4 * (size_t)Mpx * 28];            // 16.5 MB
__device__ __align__(8)  uint2  g_po[Bn * Kt * HW];                     // packed offsets
__device__ __align__(16) float4 g_pw[Bn * Kt * HW];                     // corner weights
__device__ float          g_sums[2 * CHO];                              // s, s2 partials
__device__ float          g_stats[2 * CHO];                             // scale, shift

// packed f32x2 helpers (PTX 8.6+, sm_100 family)
__device__ __forceinline__ void ffma2(ull& d, ull a, ull b) {
    asm("fma.rn.f32x2 %0, %1, %2, %0;" : "+l"(d) : "l"(a), "l"(b));
}
__device__ __forceinline__ ull splat2(float v) {
    ull r;
    asm("mov.b64 %0, {%1, %1};" : "=l"(r) : "f"(v));
    return r;
}
__device__ __forceinline__ void unpack2(ull v, float& lo, float& hi) {
    asm("mov.b64 {%0, %1}, %2;" : "=f"(lo), "=f"(hi) : "l"(v));
}

// ---------------------------------------------------------------------------
// Kernel 1: offset conv partials (quarter channels per block, 2 px/thread).
// grid (Mpx/256, 4), block 128. FFMA2 (f32x2) with oc-paired accumulators;
// smem weight pairs read directly as ulonglong2 (LDS.128 = 2 packed pairs).
// ---------------------------------------------------------------------------
#define OC  27
#define OCP 32

__global__ void __launch_bounds__(128) k_offset(
    const float* __restrict__ x,
    const float* __restrict__ w_off)
{
    __shared__ float ws[32 * 9 * OCP];
    int p0 = blockIdx.x * 256 + threadIdx.x;       // grid.x = 144
    int b  = (blockIdx.x * 256) / HW;              // whole block in one image
    int cbase = blockIdx.y * 64;                   // channel quarter

    int hw0 = p0 % HW, h0 = hw0 / Wd, w0 = hw0 % Wd;
    int hw1 = (p0 + 128) % HW, h1 = hw1 / Wd, w1 = hw1 % Wd;

    ull acc2[2][14];
#pragma unroll
    for (int q = 0; q < 2; q++)
#pragma unroll
        for (int i = 0; i < 14; i++) acc2[q][i] = 0ULL;

    for (int cq = 0; cq < 2; cq++) {
        int c0 = cbase + cq * 32;
        __syncthreads();
        for (int i = threadIdx.x; i < 32 * 9 * OC; i += 128) {
            int oc = i % OC;
            int ct = i / OC;
            ws[ct * OCP + oc] = w_off[(oc * CHI + c0 + ct / 9) * 9 + (ct % 9)];
        }
        __syncthreads();

        const float* xb = x + ((size_t)b * CHI + c0) * HW;
        for (int cc = 0; cc < 32; cc++) {
            const float* xc = xb + cc * HW;
            float xv0[9], xv1[9];
#pragma unroll
            for (int ty = 0; ty < 3; ty++) {
                int ya = h0 + ty - 1, yb2 = h1 + ty - 1;
                bool yva = ((unsigned)ya < (unsigned)Hd);
                bool yvb = ((unsigned)yb2 < (unsigned)Hd);
#pragma unroll
                for (int tx = 0; tx < 3; tx++) {
                    int xa = w0 + tx - 1, xb2 = w1 + tx - 1;
                    xv0[ty * 3 + tx] = (yva && (unsigned)xa < (unsigned)Wd)
                                     ? xc[ya * Wd + xa] : 0.f;
                    xv1[ty * 3 + tx] = (yvb && (unsigned)xb2 < (unsigned)Wd)
                                     ? xc[yb2 * Wd + xb2] : 0.f;
                }
            }
#pragma unroll
            for (int t = 0; t < 9; t++) {
                const ulonglong2* wr = (const ulonglong2*)&ws[(cc * 9 + t) * OCP];
                ull xs0 = splat2(xv0[t]);
                ull xs1 = splat2(xv1[t]);
#pragma unroll
                for (int j = 0; j < 7; j++) {
                    ulonglong2 wp = wr[j];
                    ffma2(acc2[0][2*j],     wp.x, xs0);
                    ffma2(acc2[0][2*j + 1], wp.y, xs0);
                    ffma2(acc2[1][2*j],     wp.x, xs1);
                    ffma2(acc2[1][2*j + 1], wp.y, xs1);
                }
            }
        }
    }

#pragma unroll
    for (int q = 0; q < 2; q++) {
        float a[28];
#pragma unroll
        for (int i = 0; i < 14; i++) unpack2(acc2[q][i], a[2*i], a[2*i + 1]);
        int p = p0 + q * 128;
        float4* dst = (float4*)(g_part + ((size_t)blockIdx.y * Mpx + p) * 28);
#pragma unroll
        for (int j = 0; j < 7; j++)
            dst[j] = make_float4(a[4*j], a[4*j+1], a[4*j+2], a[4*j+3]);
    }
}

// ---------------------------------------------------------------------------
// Kernel 1b: combine 4 channel-quarter partials + bias -> packed tap params.
// ---------------------------------------------------------------------------
__global__ void __launch_bounds__(256) k_taps(const float* __restrict__ b_off)
{
    int p  = blockIdx.x * 256 + threadIdx.x;
    int b  = p / HW, hw = p % HW;
    int h  = hw / Wd, w = hw % Wd;

    float acc[28];
#pragma unroll
    for (int j = 0; j < 7; j++) {
        float4 s = make_float4(0.f, 0.f, 0.f, 0.f);
#pragma unroll
        for (int q = 0; q < 4; q++) {
            float4 u = ((const float4*)(g_part + ((size_t)q * Mpx + p) * 28))[j];
            s.x += u.x; s.y += u.y; s.z += u.z; s.w += u.w;
        }
        acc[4*j+0] = s.x;  acc[4*j+1] = s.y;
        acc[4*j+2] = s.z;  acc[4*j+3] = s.w;
    }

#pragma unroll
    for (int k = 0; k < Kt; k++) {
        float dy = acc[2 * k]     + b_off[2 * k];
        float dx = acc[2 * k + 1] + b_off[2 * k + 1];
        float mz = acc[18 + k]    + b_off[18 + k];
        float m  = 1.f / (1.f + expf(-mz));

        float py = dy + (float)(h + k / 3 - 1);
        float px = dx + (float)(w + k % 3 - 1);
        float fy = floorf(py), fx = floorf(px);
        float ly = py - fy,    lx = px - fx;
        int y0 = (int)fy, x0 = (int)fx, y1 = y0 + 1, x1 = x0 + 1;

        float vy0 = ((unsigned)y0 < (unsigned)Hd) ? 1.f : 0.f;
        float vy1 = ((unsigned)y1 < (unsigned)Hd) ? 1.f : 0.f;
        float vx0 = ((unsigned)x0 < (unsigned)Wd) ? 1.f : 0.f;
        float vx1 = ((unsigned)x1 < (unsigned)Wd) ? 1.f : 0.f;

        int y0c = min(max(y0, 0), Hd - 1), y1c = min(max(y1, 0), Hd - 1);
        int x0c = min(max(x0, 0), Wd - 1), x1c = min(max(x1, 0), Wd - 1);

        unsigned o00 = (unsigned)(y0c * Wd + x0c);
        unsigned o01 = (unsigned)(y0c * Wd + x1c);
        unsigned o10 = (unsigned)(y1c * Wd + x0c);
        unsigned o11 = (unsigned)(y1c * Wd + x1c);

        int idx = (b * Kt + k) * HW + hw;
        g_po[idx] = make_uint2(o00 | (o01 << 16), o10 | (o11 << 16));
        g_pw[idx] = make_float4(
            (1.f - ly) * (1.f - lx) * vy0 * vx0 * m,
            (1.f - ly) * lx         * vy0 * vx1 * m,
            ly * (1.f - lx)         * vy1 * vx0 * m,
            ly * lx                 * vy1 * vx1 * m);
    }
}

// ---------------------------------------------------------------------------
// Kernel 2: w_conv -> fp16, [CHO][KD] K-major. Block 0 zeros all 512 g_sums.
// ---------------------------------------------------------------------------
__global__ void __launch_bounds__(256) k_wsplit(const float* __restrict__ w)
{
    int i = blockIdx.x * 256 + threadIdx.x;
    if (blockIdx.x == 0) {
        g_sums[threadIdx.x]       = 0.f;
        g_sums[threadIdx.x + 256] = 0.f;
    }
    g_wh[i] = __half_as_ushort(__float2half_rn(w[i]));
}

// ---------------------------------------------------------------------------
// Kernel 3: deformable im2col -> fp16, K-major [pixel][KD].
// Thread = (pixel, 8-channel chunk); gathers batched per tap for deep MLP.
// ---------------------------------------------------------------------------
__global__ void __launch_bounds__(256) k_cols(const float* __restrict__ x)
{
    int p  = blockIdx.x * 256 + threadIdx.x;   // grid.x = 144
    int c0 = blockIdx.y * 8;                   // grid.y = 32
    int b  = p / HW, hw = p % HW;
    const float* xb = x + ((size_t)b * CHI + c0) * HW;

    unsigned buf[36];
#pragma unroll
    for (int j = 0; j < 36; j++) buf[j] = 0u;

#pragma unroll
    for (int k = 0; k < Kt; k++) {
        int idx = (b * Kt + k) * HW + hw;
        uint2  po = __ldg(&g_po[idx]);
        float4 pw = __ldg(&g_pw[idx]);
        int o00 = po.x & 0xffff, o01 = po.x >> 16;
        int o10 = po.y & 0xffff, o11 = po.y >> 16;

        float g0[8], g1[8], g2[8], g3[8];
#pragma unroll
        for (int cc = 0; cc < 8; cc++) {
            const float* xc = xb + cc * HW;
            g0[cc] = __ldg(xc + o00);
            g1[cc] = __ldg(xc + o01);
            g2[cc] = __ldg(xc + o10);
            g3[cc] = __ldg(xc + o11);
        }
#pragma unroll
        for (int cc = 0; cc < 8; cc++) {
            float v = pw.x * g0[cc] + pw.y * g1[cc]
                    + pw.z * g2[cc] + pw.w * g3[cc];
            unsigned hb = (unsigned)__half_as_ushort(__float2half_rn(v));
            int e = cc * 9 + k;
            buf[e >> 1] |= hb << ((e & 1) * 16);
        }
    }

    uint4* dh = (uint4*)(g_cols + (size_t)p * KD + c0 * 9);
#pragma unroll
    for (int j = 0; j < 9; j++)
        dh[j] = make_uint4(buf[4*j], buf[4*j+1], buf[4*j+2], buf[4*j+3]);
}

// ---------------------------------------------------------------------------
// Kernel 4: mma.sync fp16 GEMM, single-product fp32 accumulation.
// CTA: 128 CHO x 128 pixels. 8 warps, warp tile 64x32. BK=64, 4-stage cp.async.
// Epilogue: bias, NCHW store, BN partial sums.
// ---------------------------------------------------------------------------
#define NCHUNK 36
#define TILEB  16384                 // 128 rows x 128 bytes
#define STAGEB (2 * TILEB)           // A B
#define NSTAGE 4
#define SMEMSZ (NSTAGE * STAGEB)     // 131072

#define LDM4(R0,R1,R2,R3,ADDR) \
    asm volatile("ldmatrix.sync.aligned.m8n8.x4.shared.b16 {%0,%1,%2,%3}, [%4];" \
                 : "=r"(R0),"=r"(R1),"=r"(R2),"=r"(R3) : "r"(ADDR))

#define MMA(C,A,B0,B1) \
    asm volatile("mma.sync.aligned.m16n8k16.row.col.f32.f16.f16.f32 " \
                 "{%0,%1,%2,%3},{%4,%5,%6,%7},{%8,%9},{%0,%1,%2,%3};" \
                 : "+f"((C)[0]),"+f"((C)[1]),"+f"((C)[2]),"+f"((C)[3]) \
                 : "r"((A)[0]),"r"((A)[1]),"r"((A)[2]),"r"((A)[3]),   \
                   "r"(B0),"r"(B1))

__device__ __forceinline__ void load_chunk(unsigned smBase, int stage, int chunk,
                                           int oBase, int pBase, int tid)
{
    unsigned dstBase = smBase + stage * STAGEB;
    int k0 = chunk * 64;
#pragma unroll
    for (int j = 0; j < 8; j++) {
        int i    = tid + j * 256;        // 0..2047
        int tile = i >> 10;              // 0..1
        int row  = (i >> 3) & 127;
        int u    = i & 7;
        const unsigned short* src = tile ? g_cols : g_wh;
        int rbase = tile ? pBase : oBase;
        const char* g = (const char*)src + ((size_t)(rbase + row) * KD + k0) * 2 + u * 16;
        unsigned d = dstBase + tile * TILEB + row * 128 + ((u ^ (row & 7)) * 16);
        asm volatile("cp.async.cg.shared.global [%0], [%1], 16;" :: "r"(d), "l"(g));
    }
    asm volatile("cp.async.commit_group;" ::: "memory");
}

__global__ void __launch_bounds__(256, 1) k_gemm(
    const float* __restrict__ bconv,
    float* __restrict__ out)
{
    extern __shared__ char sm[];
    unsigned smBase = (unsigned)__cvta_generic_to_shared(sm);

    int tid = threadIdx.x, lane = tid & 31, wid = tid >> 5;
    int wm = wid & 1;            // m half (64 rows)
    int wn = wid >> 1;           // n quarter (32 pixels)
    int pBase = blockIdx.x * 128;
    int oBase = blockIdx.y * 128;

    // ldmatrix per-lane geometry
    unsigned aRL = ((lane >> 3) & 1) * 8 + (lane & 7);   // A: row-in-tile16
    unsigned aU  = lane >> 4;                            // A: k8 unit
    unsigned bRL = ((lane >> 4) & 1) * 8 + (lane & 7);   // B: row-in-tile16
    unsigned bU  = (lane >> 3) & 1;                      // B: k8 unit
    unsigned aRowOff[4], bRowOff[2];
#pragma unroll
    for (int mt = 0; mt < 4; mt++) aRowOff[mt] = (wm * 64 + mt * 16 + aRL) * 128;
#pragma unroll
    for (int nt = 0; nt < 2; nt++) bRowOff[nt] = (wn * 32 + nt * 16 + bRL) * 128;
    unsigned aMsk = aRL & 7, bMsk = bRL & 7;

    float c[16][4];
#pragma unroll
    for (int i = 0; i < 16; i++)
#pragma unroll
        for (int j = 0; j < 4; j++) c[i][j] = 0.f;

    load_chunk(smBase, 0, 0, oBase, pBase, tid);
    load_chunk(smBase, 1, 1, oBase, pBase, tid);
    load_chunk(smBase, 2, 2, oBase, pBase, tid);

    for (int ch = 0; ch < NCHUNK; ch++) {
        int st = ch % NSTAGE;
        if (ch + 2 < NCHUNK) {
            asm volatile("cp.async.wait_group 2;" ::: "memory");
        } else if (ch + 1 < NCHUNK) {
            asm volatile("cp.async.wait_group 1;" ::: "memory");
        } else {
            asm volatile("cp.async.wait_group 0;" ::: "memory");
        }
        __syncthreads();
        if (ch + 3 < NCHUNK)
            load_chunk(smBase, (ch + 3) % NSTAGE, ch + 3, oBase, pBase, tid);

        unsigned base = smBase + st * STAGEB;
        unsigned sA = base, sB = base + TILEB;

#pragma unroll
        for (int kk = 0; kk < 4; kk++) {
            unsigned ua = ((kk * 2 + aU) ^ aMsk) * 16;
            unsigned ub = ((kk * 2 + bU) ^ bMsk) * 16;

            unsigned ah[4][4], bh[2][4];
#pragma unroll
            for (int mt = 0; mt < 4; mt++)
                LDM4(ah[mt][0], ah[mt][1], ah[mt][2], ah[mt][3], sA + aRowOff[mt] + ua);
#pragma unroll
            for (int nt = 0; nt < 2; nt++)
                LDM4(bh[nt][0], bh[nt][1], bh[nt][2], bh[nt][3], sB + bRowOff[nt] + ub);

#pragma unroll
            for (int mt = 0; mt < 4; mt++)
#pragma unroll
                for (int nt = 0; nt < 4; nt++) {
                    int n2 = nt >> 1, jj = (nt & 1) * 2;
                    MMA(c[mt * 4 + nt], ah[mt], bh[n2][jj], bh[n2][jj + 1]);
                }
        }
        __syncthreads();
    }

    // Epilogue: + bias, NCHW stores, BN partial sums (s, s2) per channel.
    int b = pBase / HW, hwB = pBase % HW;
#pragma unroll
    for (int mt = 0; mt < 4; mt++) {
        int o = oBase + wm * 64 + mt * 16 + (lane >> 2);
        float bias0 = bconv[o], bias8 = bconv[o + 8];
        float* r0p = out + ((size_t)b * CHO + o) * HW + hwB;
        float* r8p = r0p + 8 * HW;
        float sA2 = 0.f, qA = 0.f, sB2 = 0.f, qB = 0.f;
#pragma unroll
        for (int nt = 0; nt < 4; nt++) {
            int p = wn * 32 + nt * 8 + (lane & 3) * 2;
            float v0 = c[mt * 4 + nt][0] + bias0;
            float v1 = c[mt * 4 + nt][1] + bias0;
            float v2 = c[mt * 4 + nt][2] + bias8;
            float v3 = c[mt * 4 + nt][3] + bias8;
            *(float2*)(r0p + p) = make_float2(v0, v1);
            *(float2*)(r8p + p) = make_float2(v2, v3);
            sA2 += v0 + v1;        qA += v0 * v0 + v1 * v1;
            sB2 += v2 + v3;        qB += v2 * v2 + v3 * v3;
        }
#pragma unroll
        for (int d = 1; d < 4; d <<= 1) {
            sA2 += __shfl_xor_sync(0xffffffffu, sA2, d);
            qA  += __shfl_xor_sync(0xffffffffu, qA,  d);
            sB2 += __shfl_xor_sync(0xffffffffu, sB2, d);
            qB  += __shfl_xor_sync(0xffffffffu, qB,  d);
        }
        if ((lane & 3) == 0) {
            atomicAdd(&g_sums[o],           sA2);
            atomicAdd(&g_sums[CHO + o],     qA);
            atomicAdd(&g_sums[o + 8],       sB2);
            atomicAdd(&g_sums[CHO + o + 8], qB);
        }
    }
}

// ---------------------------------------------------------------------------
// Kernel 5: finalize BN per-channel scale/shift from partial sums (1 block).
// ---------------------------------------------------------------------------
__global__ void __launch_bounds__(256) k_bnfin(
    const float* __restrict__ gamma,
    const float* __restrict__ beta)
{
    int o = threadIdx.x;
    float inv_n = 1.f / (float)(Bn * HW);
    float mean = g_sums[o] * inv_n;
    float var  = g_sums[CHO + o] * inv_n - mean * mean;
    float scale = gamma[o] * rsqrtf(var + BN_EPS);
    g_stats[o]       = scale;
    g_stats[CHO + o] = beta[o] - mean * scale;
}

// ---------------------------------------------------------------------------
// Kernel 6: in-place BN apply + ReLU.
// ---------------------------------------------------------------------------
__global__ void __launch_bounds__(256) k_bnapply(float* __restrict__ out)
{
    int i = blockIdx.x * 256 + threadIdx.x;
    int o = (i / HW) & (CHO - 1);
    float y = out[i] * g_stats[o] + g_stats[CHO + o];
    out[i] = fmaxf(y, 0.f);
}

// ---------------------------------------------------------------------------
extern "C" void kernel_launch(void* const* d_in, const int* in_sizes, int n_in,
                              void* d_out, int out_size)
{
    const float* x      = (const float*)d_in[0];
    const float* w_off  = (const float*)d_in[1];
    const float* b_off  = (const float*)d_in[2];
    const float* w_conv = (const float*)d_in[3];
    const float* b_conv = (const float*)d_in[4];
    const float* gamma  = (const float*)d_in[5];
    const float* beta   = (const float*)d_in[6];
    float* out = (float*)d_out;

    cudaFuncSetAttribute(k_gemm, cudaFuncAttributeMaxDynamicSharedMemorySize,
                         SMEMSZ);

    dim3 goff(Mpx / 256, 4);
    k_offset<<<goff, 128>>>(x, w_off);
    k_taps<<<Mpx / 256, 256>>>(b_off);
    k_wsplit<<<(CHO * KD) / 256, 256>>>(w_conv);

    dim3 gcols(Mpx / 256, CHI / 8);
    k_cols<<<gcols, 256>>>(x);

    dim3 ggemm(Mpx / 128, CHO / 128);
    k_gemm<<<ggemm, 256, SMEMSZ>>>(b_conv, out);

    k_bnfin<<<1, 256>>>(gamma, beta);
    k_bnapply<<<(size_t)Bn * CHO * HW / 256, 256>>>(out);
}